// round 4
// baseline (speedup 1.0000x reference)
#include <cuda_runtime.h>
#include <cuda_bf16.h>
#include <math.h>

// ---------------- problem constants ----------------
#define NB 32
#define NS 512
#define NTOK (NB*NS)          // 16384
#define OBSD 256
#define ACTD 32
#define HIDD 2048
#define LATD 256
#define KCODE 4096
#define CIND (OBSD+ACTD)      // 288

// output layout (float32, tuple order flattened)
#define OFF_RECON 0
#define OFF_TOK   (NTOK*OBSD)
#define OFF_Q     (OFF_TOK + NTOK)
#define OFF_LAT   (OFF_Q + NTOK*LATD)
#define OFF_SCAL  (OFF_LAT + NTOK*LATD)

// ---------------- scratch ----------------
__device__ float g_xcat[NTOK*CIND];
__device__ float g_h1[NTOK*HIDD];
__device__ float g_h2[NTOK*HIDD];
__device__ float g_scores[(size_t)NTOK*KCODE];
__device__ float g_embT[LATD*KCODE];
__device__ float g_e2[KCODE];
__device__ float g_x2[NTOK];
__device__ int   g_tok[NTOK];
__device__ double g_qsum;
__device__ double g_rsum;

// ---------------- init ----------------
__global__ void init_k() { g_qsum = 0.0; g_rsum = 0.0; }

// ---------------- XLA-GPU-style row reduce of sum(x*x) over width 256 -----
// warp per row; lane l accumulates elems l, l+32, ..., l+224 sequentially
// (mul.rn then add.rn, no fma), then shfl_down tree 16/8/4/2/1.
__global__ void rowsq_k(const float* __restrict__ X, float* __restrict__ out, int rows) {
    int row = blockIdx.x * (blockDim.x >> 5) + (threadIdx.x >> 5);
    int l = threadIdx.x & 31;
    if (row >= rows) return;
    const float* x = X + (size_t)row * 256;
    float acc = 0.f;
    #pragma unroll
    for (int t = 0; t < 8; t++) {
        float v = x[l + 32*t];
        acc = __fadd_rn(acc, __fmul_rn(v, v));
    }
    acc = __fadd_rn(acc, __shfl_down_sync(0xffffffffu, acc, 16));
    acc = __fadd_rn(acc, __shfl_down_sync(0xffffffffu, acc, 8));
    acc = __fadd_rn(acc, __shfl_down_sync(0xffffffffu, acc, 4));
    acc = __fadd_rn(acc, __shfl_down_sync(0xffffffffu, acc, 2));
    acc = __fadd_rn(acc, __shfl_down_sync(0xffffffffu, acc, 1));
    if (l == 0) out[row] = acc;
}

__global__ void transpose_emb_k(const float* __restrict__ emb) {
    int id = blockIdx.x * 256 + threadIdx.x;
    if (id >= KCODE*LATD) return;
    int j = id >> 8;
    int k = id & 255;
    g_embT[(size_t)k*KCODE + j] = emb[id];
}

__global__ void concat_enc_k(const float* __restrict__ obs, const float* __restrict__ act) {
    int id = blockIdx.x * 256 + threadIdx.x;
    if (id >= NTOK*CIND) return;
    int i = id / CIND;
    int c = id - i*CIND;
    float v = (c < OBSD) ? obs[(size_t)i*OBSD + c] : act[(size_t)i*ACTD + (c - OBSD)];
    g_xcat[id] = v;
}

// ---------------- exact-fp32 SGEMM: C = epilogue(A[M,K] @ W[K,N]) --------
// Per output: single accumulator, strictly ascending-k FFMA chain (matches
// cuBLAS fp32 accumulation bitwise). Software-pipelined global loads.
// MODE 0: relu(acc + v1[n]);  MODE 1: acc + v1[n];
// MODE 2: fl(fl(v1[m] - 2*acc) + v2[n])   (quantizer scores)
template<int MODE>
__global__ __launch_bounds__(256)
void gemm_k(const float* __restrict__ A, const float* __restrict__ W,
            const float* __restrict__ v1, const float* __restrict__ v2,
            float* __restrict__ C, int M, int N, int K)
{
    __shared__ float As[8][128];
    __shared__ float Bs[8][128];
    const int tid = threadIdx.x;
    const int tx = tid & 15, ty = tid >> 4;
    const int m0 = blockIdx.y * 128, n0 = blockIdx.x * 128;

    float acc[8][8];
    #pragma unroll
    for (int i = 0; i < 8; i++)
        #pragma unroll
        for (int j = 0; j < 8; j++) acc[i][j] = 0.f;

    const int arow  = tid >> 1;
    const int ahalf = (tid & 1) * 4;
    const int bk = tid >> 5;
    const int bc = (tid & 31) * 4;
    const float* Aptr = A + (size_t)(m0 + arow) * K + ahalf;
    const float* Wptr = W + (size_t)bk * N + n0 + bc;

    // prologue: first tile's global loads
    float4 av = *(const float4*)(Aptr);
    float4 bv = *(const float4*)(Wptr);

    for (int k0 = 0; k0 < K; k0 += 8) {
        As[ahalf+0][arow] = av.x;
        As[ahalf+1][arow] = av.y;
        As[ahalf+2][arow] = av.z;
        As[ahalf+3][arow] = av.w;
        *(float4*)&Bs[bk][bc] = bv;
        __syncthreads();

        // prefetch next tile while computing this one
        if (k0 + 8 < K) {
            av = *(const float4*)(Aptr + k0 + 8);
            bv = *(const float4*)(Wptr + (size_t)(k0 + 8) * N);
        }

        #pragma unroll
        for (int kk = 0; kk < 8; kk++) {
            float a[8], b[8];
            #pragma unroll
            for (int i = 0; i < 8; i++) a[i] = As[kk][ty*8 + i];
            #pragma unroll
            for (int j = 0; j < 8; j++) b[j] = Bs[kk][tx*8 + j];
            #pragma unroll
            for (int i = 0; i < 8; i++)
                #pragma unroll
                for (int j = 0; j < 8; j++)
                    acc[i][j] = __fmaf_rn(a[i], b[j], acc[i][j]);
        }
        __syncthreads();
    }

    #pragma unroll
    for (int i = 0; i < 8; i++) {
        int row = m0 + ty*8 + i;
        #pragma unroll
        for (int j4 = 0; j4 < 8; j4 += 4) {
            float4 v4;
            float* pv = &v4.x;
            #pragma unroll
            for (int j = 0; j < 4; j++) {
                int col = n0 + tx*8 + j4 + j;
                float a = acc[i][j4+j];
                float v;
                if (MODE == 2) {
                    v = __fadd_rn(v1[row], -2.0f * a);   // *2 exact
                    v = __fadd_rn(v, v2[col]);
                } else {
                    v = __fadd_rn(a, v1[col]);
                    if (MODE == 0) v = fmaxf(v, 0.0f);
                }
                pv[j] = v;
            }
            *(float4*)&C[(size_t)row*N + n0 + tx*8 + j4] = v4;
        }
    }
}

// ---------------- row argmin (first-index tie break) -------------
__global__ void row_argmin_k(const float* __restrict__ S, int* __restrict__ tok) {
    int row = blockIdx.x * blockDim.y + threadIdx.y;
    int lane = threadIdx.x;
    const float* rr = S + (size_t)row * KCODE;
    unsigned long long best = ~0ULL;
    for (int j = lane; j < KCODE; j += 32) {
        float s = rr[j];
        unsigned u = __float_as_uint(s);
        u = (u & 0x80000000u) ? ~u : (u | 0x80000000u);   // order-preserving
        unsigned long long key = ((unsigned long long)u << 32) | (unsigned)j;
        best = min(best, key);
    }
    #pragma unroll
    for (int o = 16; o > 0; o >>= 1) {
        unsigned long long other = __shfl_xor_sync(0xffffffffu, best, o);
        best = min(best, other);
    }
    if (lane == 0) tok[row] = (int)(best & 0xFFFFFFFFu);
}

// ---------------- quantize ----------------
__global__ void quant_k(const float* __restrict__ lat, const float* __restrict__ emb,
                        float* __restrict__ qout, float* __restrict__ tokout)
{
    int i = blockIdx.x;
    int t = threadIdx.x;
    int idx = g_tok[i];
    float q = emb[(size_t)idx*LATD + t];
    float z = lat[(size_t)i*LATD + t];
    float d    = __fadd_rn(q, -z);
    float qste = __fadd_rn(z, d);
    qout[(size_t)i*LATD + t] = qste;
    g_xcat[(size_t)i*CIND + t] = qste;   // actions already in place from concat_enc
    if (t == 0) tokout[i] = (float)idx;

    float dl = z - q;
    float v = dl*dl;
    #pragma unroll
    for (int o = 16; o > 0; o >>= 1) v += __shfl_xor_sync(0xffffffffu, v, o);
    __shared__ float ws[8];
    int lane = t & 31, w = t >> 5;
    if (lane == 0) ws[w] = v;
    __syncthreads();
    if (t == 0) {
        float s = 0.f;
        #pragma unroll
        for (int k = 0; k < 8; k++) s += ws[k];
        atomicAdd(&g_qsum, (double)s);
    }
}

// ---------------- recon loss ----------------
__global__ void rloss_k(const float* __restrict__ recon, const float* __restrict__ obs) {
    int base = (blockIdx.x * 256 + threadIdx.x) * 4;
    float v = 0.f;
    #pragma unroll
    for (int k = 0; k < 4; k++) {
        float d = recon[base + k] - obs[base + k];
        v = __fmaf_rn(d, d, v);
    }
    #pragma unroll
    for (int o = 16; o > 0; o >>= 1) v += __shfl_xor_sync(0xffffffffu, v, o);
    __shared__ float ws[8];
    int lane = threadIdx.x & 31, w = threadIdx.x >> 5;
    if (lane == 0) ws[w] = v;
    __syncthreads();
    if (threadIdx.x == 0) {
        float s = 0.f;
        #pragma unroll
        for (int k = 0; k < 8; k++) s += ws[k];
        atomicAdd(&g_rsum, (double)s);
    }
}

__global__ void finalize_k(float* __restrict__ scal) {
    const double nrec = (double)NTOK * OBSD;
    const double nlat = (double)NTOK * LATD;
    float rl     = (float)(g_rsum / nrec);
    float mean_q = (float)(g_qsum / nlat);
    float commit = mean_q * 0.25f;
    float cb     = mean_q;
    float tq     = commit + cb;
    float tl     = rl + tq;
    scal[0] = rl; scal[1] = commit; scal[2] = cb; scal[3] = tq; scal[4] = tl;
}

// ---------------- launcher ----------------
extern "C" void kernel_launch(void* const* d_in, const int* in_sizes, int n_in,
                              void* d_out, int out_size)
{
    const float* obs    = (const float*)d_in[0];
    const float* act    = (const float*)d_in[1];
    const float* enc_w1 = (const float*)d_in[2];
    const float* enc_b1 = (const float*)d_in[3];
    const float* enc_w2 = (const float*)d_in[4];
    const float* enc_b2 = (const float*)d_in[5];
    const float* enc_w3 = (const float*)d_in[6];
    const float* enc_b3 = (const float*)d_in[7];
    const float* emb    = (const float*)d_in[8];
    const float* dec_w1 = (const float*)d_in[9];
    const float* dec_b1 = (const float*)d_in[10];
    const float* dec_w2 = (const float*)d_in[11];
    const float* dec_b2 = (const float*)d_in[12];
    const float* dec_w3 = (const float*)d_in[13];
    const float* dec_b3 = (const float*)d_in[14];

    float* out    = (float*)d_out;
    float* recon  = out + OFF_RECON;
    float* tokout = out + OFF_TOK;
    float* qout   = out + OFF_Q;
    float* lat    = out + OFF_LAT;
    float* scal   = out + OFF_SCAL;

    float *p_xcat, *p_h1, *p_h2, *p_scores, *p_embT, *p_e2, *p_x2;
    int *p_tok;
    cudaGetSymbolAddress((void**)&p_xcat,   g_xcat);
    cudaGetSymbolAddress((void**)&p_h1,     g_h1);
    cudaGetSymbolAddress((void**)&p_h2,     g_h2);
    cudaGetSymbolAddress((void**)&p_scores, g_scores);
    cudaGetSymbolAddress((void**)&p_embT,   g_embT);
    cudaGetSymbolAddress((void**)&p_e2,     g_e2);
    cudaGetSymbolAddress((void**)&p_x2,     g_x2);
    cudaGetSymbolAddress((void**)&p_tok,    g_tok);

    init_k<<<1, 1>>>();
    rowsq_k<<<KCODE/8, 256>>>(emb, p_e2, KCODE);
    transpose_emb_k<<<(KCODE*LATD + 255)/256, 256>>>(emb);
    concat_enc_k<<<(NTOK*CIND + 255)/256, 256>>>(obs, act);

    // encoder (exact fp32, ascending-k FMA chain)
    gemm_k<0><<<dim3(HIDD/128, NTOK/128), 256>>>(p_xcat, enc_w1, enc_b1, nullptr, p_h1, NTOK, HIDD, CIND);
    gemm_k<0><<<dim3(HIDD/128, NTOK/128), 256>>>(p_h1,   enc_w2, enc_b2, nullptr, p_h2, NTOK, HIDD, HIDD);
    gemm_k<1><<<dim3(LATD/128, NTOK/128), 256>>>(p_h2,   enc_w3, enc_b3, nullptr, lat,  NTOK, LATD, HIDD);

    // quantizer: scores = fl(fl(x2 - 2*dot) + e2), argmin first-index
    rowsq_k<<<NTOK/8, 256>>>(lat, p_x2, NTOK);
    gemm_k<2><<<dim3(KCODE/128, NTOK/128), 256>>>(lat, p_embT, p_x2, p_e2, p_scores, NTOK, KCODE, LATD);
    row_argmin_k<<<NTOK/8, dim3(32, 8)>>>(p_scores, p_tok);
    quant_k<<<NTOK, 256>>>(lat, emb, qout, tokout);

    // decoder
    gemm_k<0><<<dim3(HIDD/128, NTOK/128), 256>>>(p_xcat, dec_w1, dec_b1, nullptr, p_h1, NTOK, HIDD, CIND);
    gemm_k<0><<<dim3(HIDD/128, NTOK/128), 256>>>(p_h1,   dec_w2, dec_b2, nullptr, p_h2, NTOK, HIDD, HIDD);
    gemm_k<1><<<dim3(OBSD/128, NTOK/128), 256>>>(p_h2,   dec_w3, dec_b3, nullptr, recon, NTOK, OBSD, HIDD);

    rloss_k<<<(NTOK*OBSD)/(256*4), 256>>>(recon, obs);
    finalize_k<<<1, 1>>>(scal);
    (void)in_sizes; (void)n_in; (void)out_size;
}

// round 6
// speedup vs baseline: 1.4482x; 1.4482x over previous
#include <cuda_runtime.h>
#include <cuda_bf16.h>
#include <math.h>

// ---------------- problem constants ----------------
#define NB 32
#define NS 512
#define NTOK (NB*NS)          // 16384
#define OBSD 256
#define ACTD 32
#define HIDD 2048
#define LATD 256
#define KCODE 4096
#define CIND (OBSD+ACTD)      // 288

// output layout (float32, tuple order flattened)
#define OFF_RECON 0
#define OFF_TOK   (NTOK*OBSD)
#define OFF_Q     (OFF_TOK + NTOK)
#define OFF_LAT   (OFF_Q + NTOK*LATD)
#define OFF_SCAL  (OFF_LAT + NTOK*LATD)

// ---------------- scratch ----------------
__device__ float g_xcat[NTOK*CIND];
__device__ float g_h1[NTOK*HIDD];
__device__ float g_h2[NTOK*HIDD];
__device__ float g_embT[LATD*KCODE];
__device__ float g_e2[KCODE];
__device__ float g_x2[NTOK];
__device__ unsigned long long g_best[NTOK];
__device__ double g_qsum;
__device__ double g_rsum;

// ---------------- tf32 helpers ----------------
__device__ __forceinline__ unsigned f2tf32(float x) {
    unsigned y;
    asm("cvt.rna.tf32.f32 %0, %1;" : "=r"(y) : "f"(x));
    return y;
}
__device__ __forceinline__ void mma_tf32(float* d, const unsigned* a, const unsigned* b) {
    asm volatile(
        "mma.sync.aligned.m16n8k8.row.col.f32.tf32.tf32.f32 "
        "{%0,%1,%2,%3}, {%4,%5,%6,%7}, {%8,%9}, {%0,%1,%2,%3};\n"
        : "+f"(d[0]), "+f"(d[1]), "+f"(d[2]), "+f"(d[3])
        : "r"(a[0]), "r"(a[1]), "r"(a[2]), "r"(a[3]), "r"(b[0]), "r"(b[1]));
}

// ---------------- init ----------------
__global__ void init_k() {
    int id = blockIdx.x * blockDim.x + threadIdx.x;
    if (id == 0) { g_qsum = 0.0; g_rsum = 0.0; }
    if (id < NTOK) g_best[id] = ~0ULL;
}

// ---------------- XLA-GPU-style row reduce of sum(x*x) over width 256 -----
__global__ void rowsq_k(const float* __restrict__ X, float* __restrict__ out, int rows) {
    int row = blockIdx.x * (blockDim.x >> 5) + (threadIdx.x >> 5);
    int l = threadIdx.x & 31;
    if (row >= rows) return;
    const float* x = X + (size_t)row * 256;
    float acc = 0.f;
    #pragma unroll
    for (int t = 0; t < 8; t++) {
        float v = x[l + 32*t];
        acc = __fadd_rn(acc, __fmul_rn(v, v));
    }
    acc = __fadd_rn(acc, __shfl_down_sync(0xffffffffu, acc, 16));
    acc = __fadd_rn(acc, __shfl_down_sync(0xffffffffu, acc, 8));
    acc = __fadd_rn(acc, __shfl_down_sync(0xffffffffu, acc, 4));
    acc = __fadd_rn(acc, __shfl_down_sync(0xffffffffu, acc, 2));
    acc = __fadd_rn(acc, __shfl_down_sync(0xffffffffu, acc, 1));
    if (l == 0) out[row] = acc;
}

__global__ void transpose_emb_k(const float* __restrict__ emb) {
    int id = blockIdx.x * 256 + threadIdx.x;
    if (id >= KCODE*LATD) return;
    int j = id >> 8;
    int k = id & 255;
    g_embT[(size_t)k*KCODE + j] = emb[id];
}

__global__ void concat_enc_k(const float* __restrict__ obs, const float* __restrict__ act) {
    int id = blockIdx.x * 256 + threadIdx.x;
    if (id >= NTOK*CIND) return;
    int i = id / CIND;
    int c = id - i*CIND;
    float v = (c < OBSD) ? obs[(size_t)i*OBSD + c] : act[(size_t)i*ACTD + (c - OBSD)];
    g_xcat[id] = v;
}

// ================= exact-fp32 SGEMM (bit-exact path) =====================
// Per output: single accumulator, strictly ascending-k FFMA chain.
// Double-buffered smem (one barrier per k-tile). MODE 0: relu(acc+bias);
// MODE 1: acc+bias.
template<int MODE>
__global__ __launch_bounds__(256)
void gemm_k(const float* __restrict__ A, const float* __restrict__ W,
            const float* __restrict__ bias, float* __restrict__ C,
            int M, int N, int K)
{
    __shared__ float As[2][8][128];
    __shared__ float Bs[2][8][128];
    const int tid = threadIdx.x;
    const int tx = tid & 15, ty = tid >> 4;
    const int m0 = blockIdx.y * 128, n0 = blockIdx.x * 128;

    float acc[8][8];
    #pragma unroll
    for (int i = 0; i < 8; i++)
        #pragma unroll
        for (int j = 0; j < 8; j++) acc[i][j] = 0.f;

    const int arow  = tid >> 1;
    const int ahalf = (tid & 1) * 4;
    const int bk = tid >> 5;
    const int bc = (tid & 31) * 4;
    const float* Aptr = A + (size_t)(m0 + arow) * K + ahalf;
    const float* Wptr = W + (size_t)bk * N + n0 + bc;

    // prologue: fill buffer 0
    {
        float4 av = *(const float4*)(Aptr);
        float4 bv = *(const float4*)(Wptr);
        As[0][ahalf+0][arow] = av.x;
        As[0][ahalf+1][arow] = av.y;
        As[0][ahalf+2][arow] = av.z;
        As[0][ahalf+3][arow] = av.w;
        *(float4*)&Bs[0][bk][bc] = bv;
    }
    __syncthreads();

    for (int k0 = 0; k0 < K; k0 += 8) {
        const int cur = (k0 >> 3) & 1;
        const bool more = (k0 + 8) < K;
        float4 av, bv;
        if (more) {
            av = *(const float4*)(Aptr + k0 + 8);
            bv = *(const float4*)(Wptr + (size_t)(k0 + 8) * N);
        }
        #pragma unroll
        for (int kk = 0; kk < 8; kk++) {
            float a[8], b[8];
            #pragma unroll
            for (int i = 0; i < 8; i++) a[i] = As[cur][kk][ty*8 + i];
            #pragma unroll
            for (int j = 0; j < 8; j++) b[j] = Bs[cur][kk][tx*8 + j];
            #pragma unroll
            for (int i = 0; i < 8; i++)
                #pragma unroll
                for (int j = 0; j < 8; j++)
                    acc[i][j] = __fmaf_rn(a[i], b[j], acc[i][j]);
        }
        if (more) {
            As[cur^1][ahalf+0][arow] = av.x;
            As[cur^1][ahalf+1][arow] = av.y;
            As[cur^1][ahalf+2][arow] = av.z;
            As[cur^1][ahalf+3][arow] = av.w;
            *(float4*)&Bs[cur^1][bk][bc] = bv;
        }
        __syncthreads();
    }

    #pragma unroll
    for (int i = 0; i < 8; i++) {
        int row = m0 + ty*8 + i;
        #pragma unroll
        for (int j4 = 0; j4 < 8; j4 += 4) {
            float4 v4;
            float* pv = &v4.x;
            #pragma unroll
            for (int j = 0; j < 4; j++) {
                int col = n0 + tx*8 + j4 + j;
                float v = __fadd_rn(acc[i][j4+j], bias[col]);
                if (MODE == 0) v = fmaxf(v, 0.0f);
                pv[j] = v;
            }
            *(float4*)&C[(size_t)row*N + n0 + tx*8 + j4] = v4;
        }
    }
}

// ================= scores GEMM + fused row-argmin ========================
// score(m,j) = fl(fl(x2[m] - 2*dot) + e2[j]); packed-key atomicMin per row
// reproduces global first-index argmin over the same rounded values.
__global__ __launch_bounds__(256)
void gemm_score_k(const float* __restrict__ A, const float* __restrict__ W,
                  const float* __restrict__ x2, const float* __restrict__ e2,
                  int M, int N, int K)
{
    __shared__ float As[2][8][128];
    __shared__ float Bs[2][8][128];
    const int tid = threadIdx.x;
    const int tx = tid & 15, ty = tid >> 4;
    const int m0 = blockIdx.y * 128, n0 = blockIdx.x * 128;

    float acc[8][8];
    #pragma unroll
    for (int i = 0; i < 8; i++)
        #pragma unroll
        for (int j = 0; j < 8; j++) acc[i][j] = 0.f;

    const int arow  = tid >> 1;
    const int ahalf = (tid & 1) * 4;
    const int bk = tid >> 5;
    const int bc = (tid & 31) * 4;
    const float* Aptr = A + (size_t)(m0 + arow) * K + ahalf;
    const float* Wptr = W + (size_t)bk * N + n0 + bc;

    {
        float4 av = *(const float4*)(Aptr);
        float4 bv = *(const float4*)(Wptr);
        As[0][ahalf+0][arow] = av.x;
        As[0][ahalf+1][arow] = av.y;
        As[0][ahalf+2][arow] = av.z;
        As[0][ahalf+3][arow] = av.w;
        *(float4*)&Bs[0][bk][bc] = bv;
    }
    __syncthreads();

    for (int k0 = 0; k0 < K; k0 += 8) {
        const int cur = (k0 >> 3) & 1;
        const bool more = (k0 + 8) < K;
        float4 av, bv;
        if (more) {
            av = *(const float4*)(Aptr + k0 + 8);
            bv = *(const float4*)(Wptr + (size_t)(k0 + 8) * N);
        }
        #pragma unroll
        for (int kk = 0; kk < 8; kk++) {
            float a[8], b[8];
            #pragma unroll
            for (int i = 0; i < 8; i++) a[i] = As[cur][kk][ty*8 + i];
            #pragma unroll
            for (int j = 0; j < 8; j++) b[j] = Bs[cur][kk][tx*8 + j];
            #pragma unroll
            for (int i = 0; i < 8; i++)
                #pragma unroll
                for (int j = 0; j < 8; j++)
                    acc[i][j] = __fmaf_rn(a[i], b[j], acc[i][j]);
        }
        if (more) {
            As[cur^1][ahalf+0][arow] = av.x;
            As[cur^1][ahalf+1][arow] = av.y;
            As[cur^1][ahalf+2][arow] = av.z;
            As[cur^1][ahalf+3][arow] = av.w;
            *(float4*)&Bs[cur^1][bk][bc] = bv;
        }
        __syncthreads();
    }

    // epilogue: per-row min of (score_bits, col) keys, then atomicMin
    #pragma unroll
    for (int i = 0; i < 8; i++) {
        int row = m0 + ty*8 + i;
        float xr = x2[row];
        unsigned long long best = ~0ULL;
        #pragma unroll
        for (int j = 0; j < 8; j++) {
            int col = n0 + tx*8 + j;
            float v = __fadd_rn(xr, -2.0f * acc[i][j]);
            v = __fadd_rn(v, e2[col]);
            unsigned u = __float_as_uint(v);
            u = (u & 0x80000000u) ? ~u : (u | 0x80000000u);
            unsigned long long key = ((unsigned long long)u << 32) | (unsigned)col;
            best = min(best, key);
        }
        // reduce across the 16 tx lanes sharing this row (within warp)
        #pragma unroll
        for (int o = 1; o < 16; o <<= 1) {
            unsigned long long other = __shfl_xor_sync(0xffffffffu, best, o);
            best = min(best, other);
        }
        if (tx == 0) atomicMin(&g_best[row], best);
    }
}

// ================= tf32 tensor-core GEMM (decoder path) ==================
// MODE 0: relu(acc + bias[n]);  MODE 1: acc + bias[n]
template<int MODE>
__global__ __launch_bounds__(256)
void gemm_tf32_k(const float* __restrict__ A, const float* __restrict__ W,
                 const float* __restrict__ bias, float* __restrict__ C,
                 int M, int N, int K)
{
    __shared__ unsigned As[128*36];   // [row][k] pad to 36
    __shared__ unsigned Bs[32*136];   // [k][n]  pad to 136

    const int tid  = threadIdx.x;
    const int lane = tid & 31;
    const int wid  = tid >> 5;
    const int warp_m = wid >> 2;      // 0..1
    const int warp_n = wid & 3;       // 0..3
    const int m0 = blockIdx.y * 128, n0 = blockIdx.x * 128;
    const int r = lane >> 2, c = lane & 3;

    float acc[4][4][4];
    #pragma unroll
    for (int mt = 0; mt < 4; mt++)
        #pragma unroll
        for (int nt = 0; nt < 4; nt++)
            #pragma unroll
            for (int q = 0; q < 4; q++) acc[mt][nt][q] = 0.f;

    // prefetch registers
    float4 pa[4], pb[4];
    #pragma unroll
    for (int i = 0; i < 4; i++) {
        int j = tid + 256*i;
        int row = j >> 3, c4 = (j & 7) * 4;
        pa[i] = *(const float4*)(A + (size_t)(m0 + row)*K + c4);
    }
    #pragma unroll
    for (int i = 0; i < 4; i++) {
        int j = tid + 256*i;
        int kk = j >> 5, c4 = (j & 31) * 4;
        pb[i] = *(const float4*)(W + (size_t)kk*N + n0 + c4);
    }

    for (int k0 = 0; k0 < K; k0 += 32) {
        // stage prefetched tile to smem (convert to tf32)
        #pragma unroll
        for (int i = 0; i < 4; i++) {
            int j = tid + 256*i;
            int row = j >> 3, c4 = (j & 7) * 4;
            unsigned* p = &As[row*36 + c4];
            p[0] = f2tf32(pa[i].x); p[1] = f2tf32(pa[i].y);
            p[2] = f2tf32(pa[i].z); p[3] = f2tf32(pa[i].w);
        }
        #pragma unroll
        for (int i = 0; i < 4; i++) {
            int j = tid + 256*i;
            int kk = j >> 5, c4 = (j & 31) * 4;
            unsigned* p = &Bs[kk*136 + c4];
            p[0] = f2tf32(pb[i].x); p[1] = f2tf32(pb[i].y);
            p[2] = f2tf32(pb[i].z); p[3] = f2tf32(pb[i].w);
        }
        __syncthreads();

        // prefetch next tile
        if (k0 + 32 < K) {
            #pragma unroll
            for (int i = 0; i < 4; i++) {
                int j = tid + 256*i;
                int row = j >> 3, c4 = (j & 7) * 4;
                pa[i] = *(const float4*)(A + (size_t)(m0 + row)*K + k0 + 32 + c4);
            }
            #pragma unroll
            for (int i = 0; i < 4; i++) {
                int j = tid + 256*i;
                int kk = j >> 5, c4 = (j & 31) * 4;
                pb[i] = *(const float4*)(W + (size_t)(k0 + 32 + kk)*N + n0 + c4);
            }
        }

        #pragma unroll
        for (int kk = 0; kk < 4; kk++) {
            int k8 = kk * 8;
            unsigned af[4][4], bf[4][2];
            #pragma unroll
            for (int mt = 0; mt < 4; mt++) {
                int m = warp_m*64 + mt*16;
                af[mt][0] = As[(m + r    )*36 + k8 + c    ];
                af[mt][1] = As[(m + r + 8)*36 + k8 + c    ];
                af[mt][2] = As[(m + r    )*36 + k8 + c + 4];
                af[mt][3] = As[(m + r + 8)*36 + k8 + c + 4];
            }
            #pragma unroll
            for (int nt = 0; nt < 4; nt++) {
                int n = warp_n*32 + nt*8 + r;
                bf[nt][0] = Bs[(k8 + c    )*136 + n];
                bf[nt][1] = Bs[(k8 + c + 4)*136 + n];
            }
            #pragma unroll
            for (int mt = 0; mt < 4; mt++)
                #pragma unroll
                for (int nt = 0; nt < 4; nt++)
                    mma_tf32(acc[mt][nt], af[mt], bf[nt]);
        }
        __syncthreads();
    }

    #pragma unroll
    for (int mt = 0; mt < 4; mt++) {
        #pragma unroll
        for (int nt = 0; nt < 4; nt++) {
            #pragma unroll
            for (int q = 0; q < 4; q++) {
                int row = m0 + warp_m*64 + mt*16 + r + ((q >> 1) ? 8 : 0);
                int col = n0 + warp_n*32 + nt*8 + c*2 + (q & 1);
                float v = __fadd_rn(acc[mt][nt][q], bias[col]);
                if (MODE == 0) v = fmaxf(v, 0.0f);
                C[(size_t)row*N + col] = v;
            }
        }
    }
}

// ---------------- quantize ----------------
__global__ void quant_k(const float* __restrict__ lat, const float* __restrict__ emb,
                        float* __restrict__ qout, float* __restrict__ tokout)
{
    int i = blockIdx.x;
    int t = threadIdx.x;
    int idx = (int)(g_best[i] & 0xFFFFFFFFu);
    float q = emb[(size_t)idx*LATD + t];
    float z = lat[(size_t)i*LATD + t];
    float d    = __fadd_rn(q, -z);
    float qste = __fadd_rn(z, d);
    qout[(size_t)i*LATD + t] = qste;
    g_xcat[(size_t)i*CIND + t] = qste;   // actions already in place from concat_enc
    if (t == 0) tokout[i] = (float)idx;

    float dl = z - q;
    float v = dl*dl;
    #pragma unroll
    for (int o = 16; o > 0; o >>= 1) v += __shfl_xor_sync(0xffffffffu, v, o);
    __shared__ float ws[8];
    int lane = t & 31, w = t >> 5;
    if (lane == 0) ws[w] = v;
    __syncthreads();
    if (t == 0) {
        float s = 0.f;
        #pragma unroll
        for (int k = 0; k < 8; k++) s += ws[k];
        atomicAdd(&g_qsum, (double)s);
    }
}

// ---------------- recon loss ----------------
__global__ void rloss_k(const float* __restrict__ recon, const float* __restrict__ obs) {
    int base = (blockIdx.x * 256 + threadIdx.x) * 4;
    float v = 0.f;
    #pragma unroll
    for (int k = 0; k < 4; k++) {
        float d = recon[base + k] - obs[base + k];
        v = __fmaf_rn(d, d, v);
    }
    #pragma unroll
    for (int o = 16; o > 0; o >>= 1) v += __shfl_xor_sync(0xffffffffu, v, o);
    __shared__ float ws[8];
    int lane = threadIdx.x & 31, w = threadIdx.x >> 5;
    if (lane == 0) ws[w] = v;
    __syncthreads();
    if (threadIdx.x == 0) {
        float s = 0.f;
        #pragma unroll
        for (int k = 0; k < 8; k++) s += ws[k];
        atomicAdd(&g_rsum, (double)s);
    }
}

__global__ void finalize_k(float* __restrict__ scal) {
    const double nrec = (double)NTOK * OBSD;
    const double nlat = (double)NTOK * LATD;
    float rl     = (float)(g_rsum / nrec);
    float mean_q = (float)(g_qsum / nlat);
    float commit = mean_q * 0.25f;
    float cb     = mean_q;
    float tq     = commit + cb;
    float tl     = rl + tq;
    scal[0] = rl; scal[1] = commit; scal[2] = cb; scal[3] = tq; scal[4] = tl;
}

// ---------------- launcher ----------------
extern "C" void kernel_launch(void* const* d_in, const int* in_sizes, int n_in,
                              void* d_out, int out_size)
{
    const float* obs    = (const float*)d_in[0];
    const float* act    = (const float*)d_in[1];
    const float* enc_w1 = (const float*)d_in[2];
    const float* enc_b1 = (const float*)d_in[3];
    const float* enc_w2 = (const float*)d_in[4];
    const float* enc_b2 = (const float*)d_in[5];
    const float* enc_w3 = (const float*)d_in[6];
    const float* enc_b3 = (const float*)d_in[7];
    const float* emb    = (const float*)d_in[8];
    const float* dec_w1 = (const float*)d_in[9];
    const float* dec_b1 = (const float*)d_in[10];
    const float* dec_w2 = (const float*)d_in[11];
    const float* dec_b2 = (const float*)d_in[12];
    const float* dec_w3 = (const float*)d_in[13];
    const float* dec_b3 = (const float*)d_in[14];

    float* out    = (float*)d_out;
    float* recon  = out + OFF_RECON;
    float* tokout = out + OFF_TOK;
    float* qout   = out + OFF_Q;
    float* lat    = out + OFF_LAT;
    float* scal   = out + OFF_SCAL;

    float *p_xcat, *p_h1, *p_h2, *p_embT, *p_e2, *p_x2;
    cudaGetSymbolAddress((void**)&p_xcat, g_xcat);
    cudaGetSymbolAddress((void**)&p_h1,   g_h1);
    cudaGetSymbolAddress((void**)&p_h2,   g_h2);
    cudaGetSymbolAddress((void**)&p_embT, g_embT);
    cudaGetSymbolAddress((void**)&p_e2,   g_e2);
    cudaGetSymbolAddress((void**)&p_x2,   g_x2);

    init_k<<<(NTOK + 255)/256, 256>>>();
    rowsq_k<<<KCODE/8, 256>>>(emb, p_e2, KCODE);
    transpose_emb_k<<<(KCODE*LATD + 255)/256, 256>>>(emb);
    concat_enc_k<<<(NTOK*CIND + 255)/256, 256>>>(obs, act);

    // encoder (exact fp32, ascending-k FMA chain)
    gemm_k<0><<<dim3(HIDD/128, NTOK/128), 256>>>(p_xcat, enc_w1, enc_b1, p_h1, NTOK, HIDD, CIND);
    gemm_k<0><<<dim3(HIDD/128, NTOK/128), 256>>>(p_h1,   enc_w2, enc_b2, p_h2, NTOK, HIDD, HIDD);
    gemm_k<1><<<dim3(LATD/128, NTOK/128), 256>>>(p_h2,   enc_w3, enc_b3, lat,  NTOK, LATD, HIDD);

    // quantizer: fused scores + argmin
    rowsq_k<<<NTOK/8, 256>>>(lat, p_x2, NTOK);
    gemm_score_k<<<dim3(KCODE/128, NTOK/128), 256>>>(lat, p_embT, p_x2, p_e2, NTOK, KCODE, LATD);
    quant_k<<<NTOK, 256>>>(lat, emb, qout, tokout);

    // decoder (tf32 tensor cores; only feeds recon, tolerance 1e-3)
    gemm_tf32_k<0><<<dim3(HIDD/128, NTOK/128), 256>>>(p_xcat, dec_w1, dec_b1, p_h1, NTOK, HIDD, CIND);
    gemm_tf32_k<0><<<dim3(HIDD/128, NTOK/128), 256>>>(p_h1,   dec_w2, dec_b2, p_h2, NTOK, HIDD, HIDD);
    gemm_tf32_k<1><<<dim3(OBSD/128, NTOK/128), 256>>>(p_h2,   dec_w3, dec_b3, recon, NTOK, OBSD, HIDD);

    rloss_k<<<(NTOK*OBSD)/(256*4), 256>>>(recon, obs);
    finalize_k<<<1, 1>>>(scal);
    (void)in_sizes; (void)n_in; (void)out_size;
}